// round 8
// baseline (speedup 1.0000x reference)
#include <cuda_runtime.h>
#include <math.h>

#define BB    64
#define NPTS  2048
#define SDIR  512
#define NDIRS 1536
#define QQ    1024
#define T0D   286
#define T1D   165
#define T2D   84
#define NSH   36
#define SK    8

#define C1F 18.0336880111120430f
#define C2F 36.0673760222240860f

__constant__ int c_pidx[36] = {
    0, 2, 5, 8, 12, 17, 22, 27, 32,
    38, 45, 52, 59, 66, 73, 80,
    88, 97, 106, 115, 124, 133, 142, 151, 160,
    170, 181, 192, 203, 214, 225, 236, 247, 258, 269, 280};
__constant__ float c_radii[3] = {0.4f, 0.8f, 1.2f};

// ---------------- scratch ----------------
__device__ float4 g_xp[BB * NPTS];
__device__ float  g_f[BB * NDIRS];
__device__ float  g_sh4[BB * NSH * 4];        // SH coeffs padded to 4 "channels"
__device__ float  g_E0[QQ * NSH];
__device__ float  g_rs0[QQ];                  // rowsums D_eval0 (286 cols)
__device__ float  g_rs1[QQ];                  // rowsums D_eval1 (165 cols)
__device__ float  g_rs2[QQ];                  // rowsums D_eval2 (84 cols)
__device__ float  g_Yp[BB * QQ * 32];         // eval output (pre-mix), <=32 ch
__device__ float  g_Y[BB * QQ * 64];          // mix output (BN/act applied by consumer)
__device__ float  g_m[BB * T2D * 32];         // coef output (max 84*32 vs 165*16)
__device__ float  g_ck[SK * BB * T2D * 64];   // split-K partials
__device__ float  g_part[2 * 1024 * 64];      // BN partials
__device__ float  g_scale[64];
__device__ float  g_shift[64];
__device__ float  g_t3[BB * T2D * 64];
__device__ float  g_a1[BB * 512];
__device__ float  g_a2[BB * 256];

__device__ __forceinline__ float ex2(float x) {
    float y;
    asm("ex2.approx.ftz.f32 %0, %1;" : "=f"(y) : "f"(x));
    return y;
}

// ---------------- merged prep: points + E0 gather + rowsums ----------------
__global__ void k_prep_e0(const float* __restrict__ x, const float* __restrict__ D0,
                          const float* __restrict__ D1, const float* __restrict__ D2) {
    int bx = blockIdx.x;
    if (bx < 512) {
        int i = bx * 256 + threadIdx.x;
        float a = x[3 * i], b = x[3 * i + 1], c = x[3 * i + 2];
        float n2 = a * a + b * b + c * c;
        g_xp[i] = make_float4(a * C2F, b * C2F, c * C2F, -C1F * n2);
    } else if (bx < 516) {
        int q = (bx - 512) * 256 + threadIdx.x;
        const float* row = D0 + q * T0D;
        float s = 0.f;
        for (int t = 0; t < T0D; t++) s += row[t];
        g_rs0[q] = s;
        for (int j = 0; j < NSH; j++) g_E0[q * NSH + j] = row[c_pidx[j]];
    } else if (bx < 520) {
        int q = (bx - 516) * 256 + threadIdx.x;
        const float* row = D1 + q * T1D;
        float s = 0.f;
        for (int t = 0; t < T1D; t++) s += row[t];
        g_rs1[q] = s;
    } else {
        int q = (bx - 520) * 256 + threadIdx.x;
        const float* row = D2 + q * T2D;
        float s = 0.f;
        for (int t = 0; t < T2D; t++) s += row[t];
        g_rs2[q] = s;
    }
}

// ---------------- shell densities ----------------
__global__ void __launch_bounds__(256) k_shell(const float* __restrict__ dirs) {
    __shared__ float4 sp[NPTS];  // 32 KB
    int b = blockIdx.y;
    int s = blockIdx.x * 256 + threadIdx.x;
    const float4* src = g_xp + b * NPTS;
    for (int i = threadIdx.x; i < NPTS; i += 256) sp[i] = src[i];
    __syncthreads();

    int shell = s >> 9;
    int j = s & 511;
    float r = c_radii[shell];
    const float* d = dirs + (size_t)(shell * SDIR + j) * 3;
    float cx = d[0] * r, cy = d[1] * r, cz = d[2] * r;
    float acc0 = 0.f, acc1 = 0.f;
#pragma unroll 8
    for (int i = 0; i < NPTS; i += 2) {
        float4 p = sp[i];
        float4 q = sp[i + 1];
        float t0 = fmaf(p.x, cx, fmaf(p.y, cy, fmaf(p.z, cz, p.w)));
        float t1 = fmaf(q.x, cx, fmaf(q.y, cy, fmaf(q.z, cz, q.w)));
        acc0 += ex2(t0);
        acc1 += ex2(t1);
    }
    float sc = ex2(-C1F * r * r) * (1.0f / (float)NPTS);
    g_f[b * NDIRS + s] = (acc0 + acc1) * sc;
}

// ---------------- SH projection: warp-per-output into padded [b][36][4] ----------------
__global__ void k_shproj(const float* __restrict__ A_sh) {
    int w = blockIdx.x * 8 + (threadIdx.x >> 5);   // 0 .. 64*144-1
    int l = threadIdx.x & 31;
    int b = w / 144;
    int o = w % 144;
    int shell = o / NSH;
    int j = o % NSH;
    if (shell == 3) {
        if (l == 0) g_sh4[(b * NSH + j) * 4 + 3] = 0.f;
        return;
    }
    const float* arow = A_sh + j * SDIR;
    const float* f = g_f + b * NDIRS + shell * SDIR;
    float acc = 0.f;
#pragma unroll
    for (int s = l; s < SDIR; s += 32) acc = fmaf(arow[s], f[s], acc);
#pragma unroll
    for (int st = 16; st > 0; st >>= 1)
        acc += __shfl_xor_sync(0xffffffffu, acc, st);
    if (l == 0) g_sh4[(b * NSH + j) * 4 + shell] = acc;
}

// ---------------- 2D register-tiled GEMM ----------------
// C[z][bb][m][u] = sum_{k slice} A[m][k] * act(B[bb][k][u])
// 256 threads (16x16); thread computes RM x 4 outputs; NE = N*NB = 64.
template <int N, int NB, int RM, int KT>
__global__ void __launch_bounds__(256) k_gemm2(
    const float* __restrict__ A, const float* __restrict__ Bm, float* __restrict__ C,
    int M, int K,
    const float* __restrict__ sc, const float* __restrict__ sh, int klen) {
    constexpr int NE = N * NB;      // 64
    constexpr int TM = 16 * RM;
    __shared__ __align__(16) float As[KT][TM + 8];
    __shared__ __align__(16) float Bs[KT][NE];
    int t = threadIdx.x;
    int tx = t & 15, ty = t >> 4;
    int m0 = blockIdx.x * TM;
    int bgrp = blockIdx.y * NB;
    int kbase = 0, kend = K;
    if (klen > 0) {
        kbase = blockIdx.z * klen;
        kend = min(K, kbase + klen);
    }
    float acc[RM][4];
#pragma unroll
    for (int i = 0; i < RM; i++)
#pragma unroll
        for (int jj = 0; jj < 4; jj++) acc[i][jj] = 0.f;

    for (int k0 = kbase; k0 < kend; k0 += KT) {
        constexpr int AL = (TM * KT) / 256;
#pragma unroll
        for (int e = 0; e < AL; e++) {
            int idx = t + e * 256;
            int row = idx / KT, col = idx % KT;
            int m = m0 + row, k = k0 + col;
            As[col][row] = (m < M && k < kend) ? A[(size_t)m * K + k] : 0.f;
        }
        constexpr int BL = (KT * NE) / 256;
#pragma unroll
        for (int e = 0; e < BL; e++) {
            int idx = t + e * 256;
            int kk = idx / NE, uu = idx % NE;
            int k = k0 + kk;
            float v = 0.f;
            if (k < kend) {
                int bb = bgrp + uu / N;
                int u = uu % N;
                v = Bm[((size_t)bb * K + k) * N + u];
                if (sc) {
                    v = fmaf(v, sc[u], sh[u]);
                    v = fmaxf(v, 0.3f * v);
                }
            }
            Bs[kk][uu] = v;
        }
        __syncthreads();
#pragma unroll 4
        for (int kk = 0; kk < KT; kk++) {
            float av[RM];
#pragma unroll
            for (int i = 0; i < RM; i++) av[i] = As[kk][ty * RM + i];
            float4 bv = *reinterpret_cast<const float4*>(&Bs[kk][tx * 4]);
            float bw[4] = {bv.x, bv.y, bv.z, bv.w};
#pragma unroll
            for (int i = 0; i < RM; i++)
#pragma unroll
                for (int jj = 0; jj < 4; jj++)
                    acc[i][jj] = fmaf(av[i], bw[jj], acc[i][jj]);
        }
        __syncthreads();
    }

    int uu0 = tx * 4;
    int bb = bgrp + uu0 / N;
    int ub = uu0 % N;
    size_t cbase = ((size_t)blockIdx.z * BB + bb) * M;
#pragma unroll
    for (int i = 0; i < RM; i++) {
        int m = m0 + ty * RM + i;
        if (m < M) {
#pragma unroll
            for (int jj = 0; jj < 4; jj++)
                C[(cbase + m) * N + ub + jj] = acc[i][jj];
        }
    }
}

// ---------------- mix (channel GEMM) + bias-via-rowsum + fused BN partials ----------------
// out[b][m][u] = sum_c in[b][m][c]*W[c][u] + rs[m]*bias[u]
template <int CIN, int COUT, int CN>
__global__ void __launch_bounds__(256) k_mixg(
    const float* __restrict__ in, const float* __restrict__ W, int wrows,
    const float* __restrict__ rs, const float* __restrict__ bias,
    float* __restrict__ outp, float* __restrict__ statsOut) {
    __shared__ float At[CIN][68];
    __shared__ float Ws[CIN][COUT];
    __shared__ float red[2][16][COUT];
    int t = threadIdx.x;
    int tx = t & 15, ty = t >> 4;
    int b = blockIdx.y;
    int m0 = blockIdx.x * 64;

    for (int idx = t; idx < 64 * CIN; idx += 256) {
        int r = idx / CIN, c = idx % CIN;
        At[c][r] = in[((size_t)b * QQ + m0 + r) * CIN + c];
    }
    for (int idx = t; idx < CIN * COUT; idx += 256) {
        int c = idx / COUT, u = idx % COUT;
        Ws[c][u] = (c < wrows) ? W[c * COUT + u] : 0.f;
    }
    __syncthreads();

    float acc[4][CN];
#pragma unroll
    for (int i = 0; i < 4; i++)
#pragma unroll
        for (int j = 0; j < CN; j++) acc[i][j] = 0.f;
#pragma unroll
    for (int c = 0; c < CIN; c++) {
        float av[4];
#pragma unroll
        for (int i = 0; i < 4; i++) av[i] = At[c][ty * 4 + i];
        float bw[CN];
#pragma unroll
        for (int j = 0; j < CN; j++) bw[j] = Ws[c][tx * CN + j];
#pragma unroll
        for (int i = 0; i < 4; i++)
#pragma unroll
            for (int j = 0; j < CN; j++)
                acc[i][j] = fmaf(av[i], bw[j], acc[i][j]);
    }

    float ps[CN], pq[CN];
#pragma unroll
    for (int j = 0; j < CN; j++) { ps[j] = 0.f; pq[j] = 0.f; }
#pragma unroll
    for (int i = 0; i < 4; i++) {
        int m = m0 + ty * 4 + i;
        float r = rs[m];
#pragma unroll
        for (int j = 0; j < CN; j++) {
            float v = fmaf(r, bias[tx * CN + j], acc[i][j]);
            outp[((size_t)b * QQ + m) * COUT + tx * CN + j] = v;
            ps[j] += v;
            pq[j] = fmaf(v, v, pq[j]);
        }
    }
#pragma unroll
    for (int j = 0; j < CN; j++) {
        red[0][ty][tx * CN + j] = ps[j];
        red[1][ty][tx * CN + j] = pq[j];
    }
    __syncthreads();
    if (t < COUT) {
        float s = 0.f, q = 0.f;
#pragma unroll
        for (int r = 0; r < 16; r++) {
            s += red[0][r][t];
            q += red[1][r][t];
        }
        int bid = blockIdx.y * gridDim.x + blockIdx.x;
        int nblk = gridDim.x * gridDim.y;
        statsOut[bid * COUT + t] = s;
        statsOut[nblk * COUT + bid * COUT + t] = q;
    }
}

// ---------------- split-K reduce ----------------
__global__ void k_reduce_sk(const float* __restrict__ src, float* __restrict__ dst,
                            int n, int stride) {
    int i = blockIdx.x * 256 + threadIdx.x;
    if (i >= n) return;
    float s = 0.f;
#pragma unroll
    for (int z = 0; z < SK; z++) s += src[(size_t)z * stride + i];
    dst[i] = s;
}

// ---------------- BN finalize ----------------
__global__ void k_stats_fin(int U, int nblk, const float* __restrict__ g,
                            const float* __restrict__ be) {
    int u = blockIdx.x;
    int t = threadIdx.x;
    float s = 0.f, q = 0.f;
    for (int r = t; r < nblk; r += 256) {
        s += g_part[r * U + u];
        q += g_part[nblk * U + r * U + u];
    }
    __shared__ float ss[256], qq[256];
    ss[t] = s; qq[t] = q;
    __syncthreads();
    for (int st = 128; st > 0; st >>= 1) {
        if (t < st) { ss[t] += ss[t + st]; qq[t] += qq[t + st]; }
        __syncthreads();
    }
    if (t == 0) {
        const float inv = 1.0f / (float)(BB * QQ);
        float m = ss[0] * inv;
        float var = qq[0] * inv - m * m;
        float rsq = rsqrtf(var + 1e-3f);
        float scv = rsq * g[u];
        g_scale[u] = scv;
        g_shift[u] = be[u] - m * scv;
    }
}

// ---------------- fused degree-norms + FC1 ----------------
__global__ void k_fc1n(const float* __restrict__ W, const float* __restrict__ bias,
                       float* __restrict__ out) {
    __shared__ float h[256];
    int b = blockIdx.x;
    int t = threadIdx.x;   // 512
    if (t < 256) {
        int blk = t >> 6;
        int u = t & 63;
        int off, sz;
        if (blk == 0)      { off = 0;  sz = 1; }
        else if (blk == 1) { off = 1;  sz = 9; }
        else if (blk == 2) { off = 10; sz = 25; }
        else               { off = 35; sz = 49; }
        const float* y = g_t3 + (size_t)b * T2D * 64;
        float s = 0.f;
        for (int r = 0; r < sz; r++) {
            float v = y[(off + r) * 64 + u];
            s = fmaf(v, v, s);
        }
        h[t] = sqrtf(s);
    }
    __syncthreads();
    float acc = bias[t];
    for (int i = 0; i < 256; i++) acc = fmaf(h[i], W[i * 512 + t], acc);
    out[b * 512 + t] = acc;
}

// ---------------- dense FC ----------------
__global__ void k_fc(const float* __restrict__ in, const float* __restrict__ W,
                     const float* __restrict__ bias, float* __restrict__ out,
                     int IN, int OUT) {
    __shared__ float s[512];
    int b = blockIdx.x;
    for (int i = threadIdx.x; i < IN; i += blockDim.x) s[i] = in[b * IN + i];
    __syncthreads();
    int j = threadIdx.x;
    if (j < OUT) {
        float acc = bias[j];
        for (int i = 0; i < IN; i++) acc = fmaf(s[i], W[i * OUT + j], acc);
        out[b * OUT + j] = acc;
    }
}

// ---------------- batch BN + ReLU ----------------
__global__ void k_bnrelu(float* __restrict__ a, const float* __restrict__ g,
                         const float* __restrict__ be, int F) {
    int j = blockIdx.x;
    int b = threadIdx.x;  // 64
    float v = a[b * F + j];
    __shared__ float ss[64], qq[64];
    __shared__ float sm, sr;
    ss[b] = v; qq[b] = v * v;
    __syncthreads();
    for (int st = 32; st > 0; st >>= 1) {
        if (b < st) { ss[b] += ss[b + st]; qq[b] += qq[b + st]; }
        __syncthreads();
    }
    if (b == 0) {
        float m = ss[0] * (1.0f / 64.0f);
        float var = qq[0] * (1.0f / 64.0f) - m * m;
        sm = m;
        sr = rsqrtf(var + 1e-3f);
    }
    __syncthreads();
    float y = (v - sm) * sr * g[j] + be[j];
    a[b * F + j] = y > 0.f ? y : 0.f;
}

// ---------------- output head + softmax ----------------
__global__ void k_out(const float* __restrict__ Wout, const float* __restrict__ bout,
                      float* __restrict__ out) {
    int b = blockIdx.x;
    __shared__ float h[256];
    __shared__ float lg[40];
    for (int i = threadIdx.x; i < 256; i += 64) h[i] = g_a2[b * 256 + i];
    __syncthreads();
    if (threadIdx.x < 40) {
        float acc = bout[threadIdx.x];
        for (int i = 0; i < 256; i++) acc = fmaf(h[i], Wout[i * 40 + threadIdx.x], acc);
        lg[threadIdx.x] = acc;
    }
    __syncthreads();
    if (threadIdx.x == 0) {
        float mx = -1e30f;
        for (int i = 0; i < 40; i++) mx = fmaxf(mx, lg[i]);
        float s = 0.f;
        for (int i = 0; i < 40; i++) {
            float e = __expf(lg[i] - mx);
            lg[i] = e;
            s += e;
        }
        float inv = 1.f / s;
        for (int i = 0; i < 40; i++) out[b * 40 + i] = lg[i] * inv;
    }
}

// ---------------- launch ----------------
extern "C" void kernel_launch(void* const* d_in, const int* in_sizes, int n_in,
                              void* d_out, int out_size) {
    const float* x          = (const float*)d_in[0];
    const float* shell_dirs = (const float*)d_in[1];
    const float* A_sh       = (const float*)d_in[2];
    const float* D_eval0    = (const float*)d_in[3];
    const float* D_eval1    = (const float*)d_in[4];
    const float* D_eval2    = (const float*)d_in[5];
    const float* D_coef1    = (const float*)d_in[6];
    const float* D_coef2    = (const float*)d_in[7];
    const float* D_coefL    = (const float*)d_in[8];
    const float* W0 = (const float*)d_in[9];   const float* b0 = (const float*)d_in[10];
    const float* W1 = (const float*)d_in[11];  const float* b1 = (const float*)d_in[12];
    const float* W2 = (const float*)d_in[13];  const float* b2 = (const float*)d_in[14];
    const float* g0 = (const float*)d_in[15];  const float* be0 = (const float*)d_in[16];
    const float* g1 = (const float*)d_in[17];  const float* be1 = (const float*)d_in[18];
    const float* g2 = (const float*)d_in[19];  const float* be2 = (const float*)d_in[20];
    const float* Wfc1 = (const float*)d_in[21]; const float* bfc1 = (const float*)d_in[22];
    const float* gfc1 = (const float*)d_in[23]; const float* befc1 = (const float*)d_in[24];
    const float* Wfc2 = (const float*)d_in[25]; const float* bfc2 = (const float*)d_in[26];
    const float* gfc2 = (const float*)d_in[27]; const float* befc2 = (const float*)d_in[28];
    const float* Wout = (const float*)d_in[29]; const float* bout = (const float*)d_in[30];
    float* out = (float*)d_out;

    float *pE0, *prs0, *prs1, *prs2, *psh4, *pYp, *pY, *pm, *pck, *ppart,
          *psc, *pshf, *pt3, *pa1, *pa2;
    cudaGetSymbolAddress((void**)&pE0, g_E0);
    cudaGetSymbolAddress((void**)&prs0, g_rs0);
    cudaGetSymbolAddress((void**)&prs1, g_rs1);
    cudaGetSymbolAddress((void**)&prs2, g_rs2);
    cudaGetSymbolAddress((void**)&psh4, g_sh4);
    cudaGetSymbolAddress((void**)&pYp, g_Yp);
    cudaGetSymbolAddress((void**)&pY, g_Y);
    cudaGetSymbolAddress((void**)&pm, g_m);
    cudaGetSymbolAddress((void**)&pck, g_ck);
    cudaGetSymbolAddress((void**)&ppart, g_part);
    cudaGetSymbolAddress((void**)&psc, g_scale);
    cudaGetSymbolAddress((void**)&pshf, g_shift);
    cudaGetSymbolAddress((void**)&pt3, g_t3);
    cudaGetSymbolAddress((void**)&pa1, g_a1);
    cudaGetSymbolAddress((void**)&pa2, g_a2);

    // shell embedding
    k_prep_e0<<<524, 256>>>(x, D_eval0, D_eval1, D_eval2);
    k_shell<<<dim3(6, BB), 256>>>(shell_dirs);
    k_shproj<<<(BB * 144) / 8, 256>>>(A_sh);

    // layer 0: eval at C=4(pad), then mix 4->16 (+bias via rs0, stats)
    k_gemm2<4, 16, 4, 36><<<dim3(16, 4), 256>>>(pE0, psh4, pYp, QQ, NSH,
                                                nullptr, nullptr, 0);
    k_mixg<4, 16, 1><<<dim3(16, BB), 256>>>(pYp, W0, 3, prs0, b0, pY, ppart);
    k_stats_fin<<<16, 256>>>(16, 1024, g0, be0);

    // coef1 (applies BN+LReLU on load), split-K
    k_gemm2<16, 4, 4, 32><<<dim3(3, 16, SK), 256>>>(D_coef1, pY, pck, T1D, QQ,
                                                    psc, pshf, QQ / SK);
    k_reduce_sk<<<(BB * T1D * 16 + 255) / 256, 256>>>(pck, pm, BB * T1D * 16, BB * T1D * 16);

    // layer 1: eval at C=16, mix 16->32
    k_gemm2<16, 4, 4, 32><<<dim3(16, 16), 256>>>(D_eval1, pm, pYp, QQ, T1D,
                                                 nullptr, nullptr, 0);
    k_mixg<16, 32, 2><<<dim3(16, BB), 256>>>(pYp, W1, 16, prs1, b1, pY, ppart);
    k_stats_fin<<<32, 256>>>(32, 1024, g1, be1);

    k_gemm2<32, 2, 6, 32><<<dim3(1, 32, SK), 256>>>(D_coef2, pY, pck, T2D, QQ,
                                                    psc, pshf, QQ / SK);
    k_reduce_sk<<<(BB * T2D * 32 + 255) / 256, 256>>>(pck, pm, BB * T2D * 32, BB * T2D * 32);

    // layer 2: eval at C=32, mix 32->64
    k_gemm2<32, 2, 4, 32><<<dim3(16, 32), 256>>>(D_eval2, pm, pYp, QQ, T2D,
                                                 nullptr, nullptr, 0);
    k_mixg<32, 64, 4><<<dim3(16, BB), 256>>>(pYp, W2, 32, prs2, b2, pY, ppart);
    k_stats_fin<<<64, 256>>>(64, 1024, g2, be2);

    k_gemm2<64, 1, 6, 32><<<dim3(1, 64, SK), 256>>>(D_coefL, pY, pck, T2D, QQ,
                                                    psc, pshf, QQ / SK);
    k_reduce_sk<<<(BB * T2D * 64 + 255) / 256, 256>>>(pck, pt3, BB * T2D * 64, BB * T2D * 64);

    // head
    k_fc1n<<<BB, 512>>>(Wfc1, bfc1, pa1);
    k_bnrelu<<<512, 64>>>(pa1, gfc1, befc1, 512);
    k_fc<<<BB, 256>>>(pa1, Wfc2, bfc2, pa2, 512, 256);
    k_bnrelu<<<256, 64>>>(pa2, gfc2, befc2, 256);
    k_out<<<BB, 64>>>(Wout, bout, out);
}

// round 10
// speedup vs baseline: 1.6815x; 1.6815x over previous
#include <cuda_runtime.h>
#include <math.h>

#define BB    64
#define NPTS  2048
#define SDIR  512
#define NDIRS 1536
#define QQ    1024
#define T0D   286
#define T1D   165
#define T2D   84
#define NSH   36
#define SK    8

#define C1F 18.0336880111120430f
#define C2F 36.0673760222240860f

__constant__ int c_pidx[36] = {
    0, 2, 5, 8, 12, 17, 22, 27, 32,
    38, 45, 52, 59, 66, 73, 80,
    88, 97, 106, 115, 124, 133, 142, 151, 160,
    170, 181, 192, 203, 214, 225, 236, 247, 258, 269, 280};
__constant__ float c_radii[3] = {0.4f, 0.8f, 1.2f};

// ---------------- scratch ----------------
__device__ float4 g_xp[BB * NPTS];
__device__ float  g_f[BB * NDIRS];
__device__ float  g_sh4[BB * NSH * 4];        // SH coeffs padded to 4 channels
__device__ float  g_E0[QQ * NSH];
__device__ float  g_rs0[QQ];
__device__ float  g_rs1[QQ];
__device__ float  g_rs2[QQ];
__device__ float  g_Y[BB * QQ * 64];          // eval+mix output
__device__ float  g_m[BB * T2D * 32];         // coef output (max of 165*16 / 84*32)
__device__ float  g_ck[SK * BB * T2D * 64];   // split-K partials
__device__ float  g_part[2 * 1024 * 64];      // BN partials
__device__ float  g_scale[64];
__device__ float  g_shift[64];
__device__ float  g_t3[BB * T2D * 64];
__device__ float  g_a1[BB * 512];
__device__ float  g_a2[BB * 256];

__device__ __forceinline__ float ex2(float x) {
    float y;
    asm("ex2.approx.ftz.f32 %0, %1;" : "=f"(y) : "f"(x));
    return y;
}

// ---------------- merged prep: points, E0 gather, rowsums (warp-per-row) ----------------
__global__ void k_prep_e0(const float* __restrict__ x, const float* __restrict__ D0,
                          const float* __restrict__ D1, const float* __restrict__ D2) {
    int bx = blockIdx.x;
    int t = threadIdx.x;
    if (bx < 512) {
        int i = bx * 256 + t;
        float a = x[3 * i], b = x[3 * i + 1], c = x[3 * i + 2];
        float n2 = a * a + b * b + c * c;
        g_xp[i] = make_float4(a * C2F, b * C2F, c * C2F, -C1F * n2);
    } else if (bx < 656) {
        int idx = (bx - 512) * 256 + t;     // < 1024*36 = 36864
        if (idx < QQ * NSH) {
            int q = idx / NSH, j = idx % NSH;
            g_E0[q * NSH + j] = D0[q * T0D + c_pidx[j]];
        }
    } else {
        int w = (bx - 656) * 8 + (t >> 5);  // 0..3071
        int l = t & 31;
        const float* row;
        int cols;
        float* dst;
        int q;
        if (w < 1024)      { q = w;        row = D0 + q * T0D; cols = T0D; dst = g_rs0; }
        else if (w < 2048) { q = w - 1024; row = D1 + q * T1D; cols = T1D; dst = g_rs1; }
        else               { q = w - 2048; row = D2 + q * T2D; cols = T2D; dst = g_rs2; }
        float s = 0.f;
        for (int c = l; c < cols; c += 32) s += row[c];
#pragma unroll
        for (int st = 16; st > 0; st >>= 1)
            s += __shfl_xor_sync(0xffffffffu, s, st);
        if (l == 0) dst[q] = s;
    }
}

// ---------------- shell densities ----------------
__global__ void __launch_bounds__(256) k_shell(const float* __restrict__ dirs) {
    __shared__ float4 sp[NPTS];  // 32 KB
    int b = blockIdx.y;
    int s = blockIdx.x * 256 + threadIdx.x;
    const float4* src = g_xp + b * NPTS;
    for (int i = threadIdx.x; i < NPTS; i += 256) sp[i] = src[i];
    __syncthreads();

    int shell = s >> 9;
    int j = s & 511;
    float r = c_radii[shell];
    const float* d = dirs + (size_t)(shell * SDIR + j) * 3;
    float cx = d[0] * r, cy = d[1] * r, cz = d[2] * r;
    float acc0 = 0.f, acc1 = 0.f;
#pragma unroll 8
    for (int i = 0; i < NPTS; i += 2) {
        float4 p = sp[i];
        float4 q = sp[i + 1];
        float t0 = fmaf(p.x, cx, fmaf(p.y, cy, fmaf(p.z, cz, p.w)));
        float t1 = fmaf(q.x, cx, fmaf(q.y, cy, fmaf(q.z, cz, q.w)));
        acc0 += ex2(t0);
        acc1 += ex2(t1);
    }
    float sc = ex2(-C1F * r * r) * (1.0f / (float)NPTS);
    g_f[b * NDIRS + s] = (acc0 + acc1) * sc;
}

// ---------------- SH projection: warp-per-output into padded [b][36][4] ----------------
__global__ void k_shproj(const float* __restrict__ A_sh) {
    int w = blockIdx.x * 8 + (threadIdx.x >> 5);
    int l = threadIdx.x & 31;
    int b = w / 144;
    int o = w % 144;
    int shell = o / NSH;
    int j = o % NSH;
    if (shell == 3) {
        if (l == 0) g_sh4[(b * NSH + j) * 4 + 3] = 0.f;
        return;
    }
    const float* arow = A_sh + j * SDIR;
    const float* f = g_f + b * NDIRS + shell * SDIR;
    float acc = 0.f;
#pragma unroll
    for (int s = l; s < SDIR; s += 32) acc = fmaf(arow[s], f[s], acc);
#pragma unroll
    for (int st = 16; st > 0; st >>= 1)
        acc += __shfl_xor_sync(0xffffffffu, acc, st);
    if (l == 0) g_sh4[(b * NSH + j) * 4 + shell] = acc;
}

// ---------------- fused eval GEMM + channel mix + BN partials ----------------
// Yp[bb][m][c] = sum_k A[m][k] * Bm[bb][k][c]   (eval at CIN channels, NB=64/CIN
//   batches packed in the 64-wide tile dim)
// Y[bb][m][u]  = sum_c Yp[m][c]*W[c][u] + rs[m]*bias[u]     (mix, in epilogue)
// statsOut: per-block sum/sumsq over Y columns u.
template <int CIN, int COUT, int RM, int KT>
__global__ void __launch_bounds__(256) k_evalmix(
    const float* __restrict__ A, const float* __restrict__ Bm,
    float* __restrict__ outp, int M, int K, int wrows,
    const float* __restrict__ W, const float* __restrict__ rs,
    const float* __restrict__ bias, float* __restrict__ statsOut) {
    constexpr int NB = 64 / CIN;
    constexpr int TM = 16 * RM;
    constexpr int OUTW = NB * COUT;
    __shared__ float As[KT][TM + 8];
    __shared__ float Bs[KT][64];
    __shared__ float Ws[CIN][COUT];
    __shared__ float Ys[TM][65];
    int t = threadIdx.x;
    int tx = t & 15, ty = t >> 4;
    int m0 = blockIdx.x * TM;
    int bgrp = blockIdx.y * NB;

    for (int idx = t; idx < CIN * COUT; idx += 256) {
        int c = idx / COUT, u = idx % COUT;
        Ws[c][u] = (c < wrows) ? W[c * COUT + u] : 0.f;
    }

    float acc[RM][4];
#pragma unroll
    for (int i = 0; i < RM; i++)
#pragma unroll
        for (int jj = 0; jj < 4; jj++) acc[i][jj] = 0.f;

    for (int k0 = 0; k0 < K; k0 += KT) {
        for (int idx = t; idx < TM * KT; idx += 256) {
            int row = idx / KT, col = idx % KT;
            int k = k0 + col;
            As[col][row] = (k < K) ? A[(size_t)(m0 + row) * K + k] : 0.f;
        }
        for (int idx = t; idx < KT * 64; idx += 256) {
            int kk = idx / 64, uu = idx % 64;
            int k = k0 + kk;
            float v = 0.f;
            if (k < K) {
                int bb = bgrp + uu / CIN;
                int c = uu % CIN;
                v = Bm[((size_t)bb * K + k) * CIN + c];
            }
            Bs[kk][uu] = v;
        }
        __syncthreads();
#pragma unroll 4
        for (int kk = 0; kk < KT; kk++) {
            float av[RM];
#pragma unroll
            for (int i = 0; i < RM; i++) av[i] = As[kk][ty * RM + i];
            float4 bv = *reinterpret_cast<const float4*>(&Bs[kk][tx * 4]);
            float bw[4] = {bv.x, bv.y, bv.z, bv.w};
#pragma unroll
            for (int i = 0; i < RM; i++)
#pragma unroll
                for (int jj = 0; jj < 4; jj++)
                    acc[i][jj] = fmaf(av[i], bw[jj], acc[i][jj]);
        }
        __syncthreads();
    }

    // stage eval tile
#pragma unroll
    for (int i = 0; i < RM; i++)
#pragma unroll
        for (int jj = 0; jj < 4; jj++)
            Ys[ty * RM + i][tx * 4 + jj] = acc[i][jj];
    __syncthreads();

    // mix + write + stats
    int u = t % COUT;
    float bu = bias[u];
    float ps = 0.f, pq = 0.f;
    for (int idx = t; idx < TM * OUTW; idx += 256) {
        int bbL = (idx / COUT) % NB;
        int r = idx / OUTW;
        float v = 0.f;
#pragma unroll
        for (int c = 0; c < CIN; c++)
            v = fmaf(Ys[r][bbL * CIN + c], Ws[c][u], v);
        v = fmaf(rs[m0 + r], bu, v);
        outp[((size_t)(bgrp + bbL) * M + m0 + r) * COUT + u] = v;
        ps += v;
        pq = fmaf(v, v, pq);
    }
    float* red = &As[0][0];     // >= 512 floats in all configs
    red[t] = ps;
    red[256 + t] = pq;
    __syncthreads();
    if (t < COUT) {
        float s = 0.f, q = 0.f;
        for (int r2 = t; r2 < 256; r2 += COUT) {
            s += red[r2];
            q += red[256 + r2];
        }
        int bid = blockIdx.y * gridDim.x + blockIdx.x;
        int nblk = gridDim.x * gridDim.y;
        statsOut[bid * COUT + t] = s;
        statsOut[nblk * COUT + bid * COUT + t] = q;
    }
}

// ---------------- 2D register-tiled GEMM (coef layers, split-K, BN+LReLU on load) ----------------
template <int N, int NB, int RM, int KT>
__global__ void __launch_bounds__(256) k_gemm2(
    const float* __restrict__ A, const float* __restrict__ Bm, float* __restrict__ C,
    int M, int K,
    const float* __restrict__ sc, const float* __restrict__ sh, int klen) {
    constexpr int NE = N * NB;
    constexpr int TM = 16 * RM;
    __shared__ __align__(16) float As[KT][TM + 8];
    __shared__ __align__(16) float Bs[KT][NE];
    int t = threadIdx.x;
    int tx = t & 15, ty = t >> 4;
    int m0 = blockIdx.x * TM;
    int bgrp = blockIdx.y * NB;
    int kbase = 0, kend = K;
    if (klen > 0) {
        kbase = blockIdx.z * klen;
        kend = min(K, kbase + klen);
    }
    float acc[RM][4];
#pragma unroll
    for (int i = 0; i < RM; i++)
#pragma unroll
        for (int jj = 0; jj < 4; jj++) acc[i][jj] = 0.f;

    for (int k0 = kbase; k0 < kend; k0 += KT) {
        for (int idx = t; idx < TM * KT; idx += 256) {
            int row = idx / KT, col = idx % KT;
            int m = m0 + row, k = k0 + col;
            As[col][row] = (m < M && k < kend) ? A[(size_t)m * K + k] : 0.f;
        }
        for (int idx = t; idx < KT * NE; idx += 256) {
            int kk = idx / NE, uu = idx % NE;
            int k = k0 + kk;
            float v = 0.f;
            if (k < kend) {
                int bb = bgrp + uu / N;
                int u = uu % N;
                v = Bm[((size_t)bb * K + k) * N + u];
                if (sc) {
                    v = fmaf(v, sc[u], sh[u]);
                    v = fmaxf(v, 0.3f * v);
                }
            }
            Bs[kk][uu] = v;
        }
        __syncthreads();
#pragma unroll 4
        for (int kk = 0; kk < KT; kk++) {
            float av[RM];
#pragma unroll
            for (int i = 0; i < RM; i++) av[i] = As[kk][ty * RM + i];
            float4 bv = *reinterpret_cast<const float4*>(&Bs[kk][tx * 4]);
            float bw[4] = {bv.x, bv.y, bv.z, bv.w};
#pragma unroll
            for (int i = 0; i < RM; i++)
#pragma unroll
                for (int jj = 0; jj < 4; jj++)
                    acc[i][jj] = fmaf(av[i], bw[jj], acc[i][jj]);
        }
        __syncthreads();
    }

    int uu0 = tx * 4;
    int bb = bgrp + uu0 / N;
    int ub = uu0 % N;
    size_t cbase = ((size_t)blockIdx.z * BB + bb) * M;
#pragma unroll
    for (int i = 0; i < RM; i++) {
        int m = m0 + ty * RM + i;
        if (m < M) {
#pragma unroll
            for (int jj = 0; jj < 4; jj++)
                C[(cbase + m) * N + ub + jj] = acc[i][jj];
        }
    }
}

// ---------------- split-K reduce ----------------
__global__ void k_reduce_sk(const float* __restrict__ src, float* __restrict__ dst,
                            int n, int stride) {
    int i = blockIdx.x * 256 + threadIdx.x;
    if (i >= n) return;
    float s = 0.f;
#pragma unroll
    for (int z = 0; z < SK; z++) s += src[(size_t)z * stride + i];
    dst[i] = s;
}

// ---------------- BN finalize ----------------
__global__ void k_stats_fin(int U, int nblk, const float* __restrict__ g,
                            const float* __restrict__ be) {
    int u = blockIdx.x;
    int t = threadIdx.x;
    float s = 0.f, q = 0.f;
    for (int r = t; r < nblk; r += 256) {
        s += g_part[r * U + u];
        q += g_part[nblk * U + r * U + u];
    }
    __shared__ float ss[256], qq[256];
    ss[t] = s; qq[t] = q;
    __syncthreads();
    for (int st = 128; st > 0; st >>= 1) {
        if (t < st) { ss[t] += ss[t + st]; qq[t] += qq[t + st]; }
        __syncthreads();
    }
    if (t == 0) {
        const float inv = 1.0f / (float)(BB * QQ);
        float m = ss[0] * inv;
        float var = qq[0] * inv - m * m;
        float rsq = rsqrtf(var + 1e-3f);
        float scv = rsq * g[u];
        g_scale[u] = scv;
        g_shift[u] = be[u] - m * scv;
    }
}

// ---------------- fused degree-norms + FC1 ----------------
__global__ void k_fc1n(const float* __restrict__ W, const float* __restrict__ bias,
                       float* __restrict__ out) {
    __shared__ float h[256];
    int b = blockIdx.x;
    int t = threadIdx.x;   // 512
    if (t < 256) {
        int blk = t >> 6;
        int u = t & 63;
        int off, sz;
        if (blk == 0)      { off = 0;  sz = 1; }
        else if (blk == 1) { off = 1;  sz = 9; }
        else if (blk == 2) { off = 10; sz = 25; }
        else               { off = 35; sz = 49; }
        const float* y = g_t3 + (size_t)b * T2D * 64;
        float s = 0.f;
        for (int r = 0; r < sz; r++) {
            float v = y[(off + r) * 64 + u];
            s = fmaf(v, v, s);
        }
        h[t] = sqrtf(s);
    }
    __syncthreads();
    float acc = bias[t];
    for (int i = 0; i < 256; i++) acc = fmaf(h[i], W[i * 512 + t], acc);
    out[b * 512 + t] = acc;
}

// ---------------- dense FC ----------------
__global__ void k_fc(const float* __restrict__ in, const float* __restrict__ W,
                     const float* __restrict__ bias, float* __restrict__ out,
                     int IN, int OUT) {
    __shared__ float s[512];
    int b = blockIdx.x;
    for (int i = threadIdx.x; i < IN; i += blockDim.x) s[i] = in[b * IN + i];
    __syncthreads();
    int j = threadIdx.x;
    if (j < OUT) {
        float acc = bias[j];
        for (int i = 0; i < IN; i++) acc = fmaf(s[i], W[i * OUT + j], acc);
        out[b * OUT + j] = acc;
    }
}

// ---------------- batch BN + ReLU ----------------
__global__ void k_bnrelu(float* __restrict__ a, const float* __restrict__ g,
                         const float* __restrict__ be, int F) {
    int j = blockIdx.x;
    int b = threadIdx.x;  // 64
    float v = a[b * F + j];
    __shared__ float ss[64], qq[64];
    __shared__ float sm, sr;
    ss[b] = v; qq[b] = v * v;
    __syncthreads();
    for (int st = 32; st > 0; st >>= 1) {
        if (b < st) { ss[b] += ss[b + st]; qq[b] += qq[b + st]; }
        __syncthreads();
    }
    if (b == 0) {
        float m = ss[0] * (1.0f / 64.0f);
        float var = qq[0] * (1.0f / 64.0f) - m * m;
        sm = m;
        sr = rsqrtf(var + 1e-3f);
    }
    __syncthreads();
    float y = (v - sm) * sr * g[j] + be[j];
    a[b * F + j] = y > 0.f ? y : 0.f;
}

// ---------------- output head + softmax ----------------
__global__ void k_out(const float* __restrict__ Wout, const float* __restrict__ bout,
                      float* __restrict__ out) {
    int b = blockIdx.x;
    __shared__ float h[256];
    __shared__ float lg[40];
    for (int i = threadIdx.x; i < 256; i += 64) h[i] = g_a2[b * 256 + i];
    __syncthreads();
    if (threadIdx.x < 40) {
        float acc = bout[threadIdx.x];
        for (int i = 0; i < 256; i++) acc = fmaf(h[i], Wout[i * 40 + threadIdx.x], acc);
        lg[threadIdx.x] = acc;
    }
    __syncthreads();
    if (threadIdx.x == 0) {
        float mx = -1e30f;
        for (int i = 0; i < 40; i++) mx = fmaxf(mx, lg[i]);
        float s = 0.f;
        for (int i = 0; i < 40; i++) {
            float e = __expf(lg[i] - mx);
            lg[i] = e;
            s += e;
        }
        float inv = 1.f / s;
        for (int i = 0; i < 40; i++) out[b * 40 + i] = lg[i] * inv;
    }
}

// ---------------- launch ----------------
extern "C" void kernel_launch(void* const* d_in, const int* in_sizes, int n_in,
                              void* d_out, int out_size) {
    const float* x          = (const float*)d_in[0];
    const float* shell_dirs = (const float*)d_in[1];
    const float* A_sh       = (const float*)d_in[2];
    const float* D_eval0    = (const float*)d_in[3];
    const float* D_eval1    = (const float*)d_in[4];
    const float* D_eval2    = (const float*)d_in[5];
    const float* D_coef1    = (const float*)d_in[6];
    const float* D_coef2    = (const float*)d_in[7];
    const float* D_coefL    = (const float*)d_in[8];
    const float* W0 = (const float*)d_in[9];   const float* b0 = (const float*)d_in[10];
    const float* W1 = (const float*)d_in[11];  const float* b1 = (const float*)d_in[12];
    const float* W2 = (const float*)d_in[13];  const float* b2 = (const float*)d_in[14];
    const float* g0 = (const float*)d_in[15];  const float* be0 = (const float*)d_in[16];
    const float* g1 = (const float*)d_in[17];  const float* be1 = (const float*)d_in[18];
    const float* g2 = (const float*)d_in[19];  const float* be2 = (const float*)d_in[20];
    const float* Wfc1 = (const float*)d_in[21]; const float* bfc1 = (const float*)d_in[22];
    const float* gfc1 = (const float*)d_in[23]; const float* befc1 = (const float*)d_in[24];
    const float* Wfc2 = (const float*)d_in[25]; const float* bfc2 = (const float*)d_in[26];
    const float* gfc2 = (const float*)d_in[27]; const float* befc2 = (const float*)d_in[28];
    const float* Wout = (const float*)d_in[29]; const float* bout = (const float*)d_in[30];
    float* out = (float*)d_out;

    float *pE0, *prs0, *prs1, *prs2, *psh4, *pY, *pm, *pck, *ppart,
          *psc, *pshf, *pt3, *pa1, *pa2;
    cudaGetSymbolAddress((void**)&pE0, g_E0);
    cudaGetSymbolAddress((void**)&prs0, g_rs0);
    cudaGetSymbolAddress((void**)&prs1, g_rs1);
    cudaGetSymbolAddress((void**)&prs2, g_rs2);
    cudaGetSymbolAddress((void**)&psh4, g_sh4);
    cudaGetSymbolAddress((void**)&pY, g_Y);
    cudaGetSymbolAddress((void**)&pm, g_m);
    cudaGetSymbolAddress((void**)&pck, g_ck);
    cudaGetSymbolAddress((void**)&ppart, g_part);
    cudaGetSymbolAddress((void**)&psc, g_scale);
    cudaGetSymbolAddress((void**)&pshf, g_shift);
    cudaGetSymbolAddress((void**)&pt3, g_t3);
    cudaGetSymbolAddress((void**)&pa1, g_a1);
    cudaGetSymbolAddress((void**)&pa2, g_a2);

    // shell embedding
    k_prep_e0<<<1040, 256>>>(x, D_eval0, D_eval1, D_eval2);
    k_shell<<<dim3(6, BB), 256>>>(shell_dirs);
    k_shproj<<<(BB * 144) / 8, 256>>>(A_sh);

    // layer 0: fused eval(C=4) + mix 4->16 + stats
    k_evalmix<4, 16, 1, 36><<<dim3(64, 4), 256>>>(pE0, psh4, pY, QQ, NSH, 3,
                                                  W0, prs0, b0, ppart);
    k_stats_fin<<<16, 256>>>(16, 256, g0, be0);
    k_gemm2<16, 4, 4, 32><<<dim3(3, 16, SK), 256>>>(D_coef1, pY, pck, T1D, QQ,
                                                    psc, pshf, QQ / SK);
    k_reduce_sk<<<(BB * T1D * 16 + 255) / 256, 256>>>(pck, pm, BB * T1D * 16, BB * T1D * 16);

    // layer 1: fused eval(C=16) + mix 16->32 + stats
    k_evalmix<16, 32, 2, 32><<<dim3(32, 16), 256>>>(D_eval1, pm, pY, QQ, T1D, 16,
                                                    W1, prs1, b1, ppart);
    k_stats_fin<<<32, 256>>>(32, 512, g1, be1);
    k_gemm2<32, 2, 6, 32><<<dim3(1, 32, SK), 256>>>(D_coef2, pY, pck, T2D, QQ,
                                                    psc, pshf, QQ / SK);
    k_reduce_sk<<<(BB * T2D * 32 + 255) / 256, 256>>>(pck, pm, BB * T2D * 32, BB * T2D * 32);

    // layer 2: fused eval(C=32) + mix 32->64 + stats
    k_evalmix<32, 64, 2, 32><<<dim3(32, 32), 256>>>(D_eval2, pm, pY, QQ, T2D, 32,
                                                    W2, prs2, b2, ppart);
    k_stats_fin<<<64, 256>>>(64, 1024, g2, be2);
    k_gemm2<64, 1, 6, 32><<<dim3(1, 64, SK), 256>>>(D_coefL, pY, pck, T2D, QQ,
                                                    psc, pshf, QQ / SK);
    k_reduce_sk<<<(BB * T2D * 64 + 255) / 256, 256>>>(pck, pt3, BB * T2D * 64, BB * T2D * 64);

    // head
    k_fc1n<<<BB, 512>>>(Wfc1, bfc1, pa1);
    k_bnrelu<<<512, 64>>>(pa1, gfc1, befc1, 512);
    k_fc<<<BB, 256>>>(pa1, Wfc2, bfc2, pa2, 512, 256);
    k_bnrelu<<<256, 64>>>(pa2, gfc2, befc2, 256);
    k_out<<<BB, 64>>>(Wout, bout, out);
}